// round 9
// baseline (speedup 1.0000x reference)
#include <cuda_runtime.h>
#include <cuda_bf16.h>
#include <stdint.h>
#include <math.h>

#define E_   8
#define M_   1024
#define H_   4096
#define SMAX 16384
#define CAP  2048

// mma tile config
#define RA 32u
#define RB 48u
#define BBUF 6144u
#define OFF_AL 4096u
#define OFF_BH 8192u
#define STAGEB 20480u
#define SMEM_MMA 40960

// ---------------- device scratch ------------------------------------------------
__device__ int   g_idx[SMAX];
__device__ float g_gate[SMAX];
__device__ float g_gate_sums[E_];
__device__ int   g_kept[E_];
__device__ int   g_bad1, g_bad2;
__device__ int   g_slot_token[E_ * CAP];
__device__ float g_slot_gate[E_ * CAP];
__device__ float g_h[(size_t)E_ * CAP * H_];
__device__ __align__(16) __nv_bfloat16 g_disp_hi[(size_t)E_ * CAP * M_];
__device__ __align__(16) __nv_bfloat16 g_disp_lo[(size_t)E_ * CAP * M_];
__device__ __align__(16) __nv_bfloat16 g_w1t_hi[(size_t)E_ * H_ * M_];
__device__ __align__(16) __nv_bfloat16 g_w1t_lo[(size_t)E_ * H_ * M_];
__device__ __align__(16) __nv_bfloat16 g_w2t_hi[(size_t)E_ * M_ * H_];
__device__ __align__(16) __nv_bfloat16 g_w2t_lo[(size_t)E_ * M_ * H_];
__device__ __align__(16) __nv_bfloat16 g_h_hi[(size_t)E_ * CAP * H_];
__device__ __align__(16) __nv_bfloat16 g_h_lo[(size_t)E_ * CAP * H_];

// ---------------- PTX helpers -----------------------------------------------------
#define MMA16816(c, a, b0, b1) \
    asm volatile("mma.sync.aligned.m16n8k16.row.col.f32.bf16.bf16.f32 " \
                 "{%0,%1,%2,%3}, {%4,%5,%6,%7}, {%8,%9}, {%0,%1,%2,%3};" \
                 : "+f"((c)[0]), "+f"((c)[1]), "+f"((c)[2]), "+f"((c)[3]) \
                 : "r"((a)[0]), "r"((a)[1]), "r"((a)[2]), "r"((a)[3]), "r"(b0), "r"(b1))

// ---------------- MMA mainloop: plain LDG->reg->STS double buffer -------------------
__device__ __forceinline__ void mma_mainloop(
    const __nv_bfloat16* Ah, const __nv_bfloat16* Al,
    const __nv_bfloat16* Bh, const __nv_bfloat16* Bl,
    size_t aRow0, size_t bRow0, int K,
    char* sm, int tid, float acc[2][8][4]) {

    int wid = tid >> 5, lane = tid & 31;
    int wm = wid & 3, wn = wid >> 2;
    int nst = K / 16;
    int r = tid >> 1, q = tid & 1;

    const char* pAh = (const char*)(Ah + (aRow0 + r) * (size_t)K + q * 8);
    const char* pAl = (const char*)(Al + (aRow0 + r) * (size_t)K + q * 8);
    const char* pBh = (const char*)(Bh + (bRow0 + r) * (size_t)K + q * 8);
    const char* pBl = (const char*)(Bl + (bRow0 + r) * (size_t)K + q * 8);
    uint32_t woA = (uint32_t)r * RA + (uint32_t)q * 16u;
    uint32_t woB = OFF_BH + (uint32_t)r * RB + (uint32_t)q * 16u;

    // prologue: stage 0
    uint4 vAh = *(const uint4*)pAh;
    uint4 vAl = *(const uint4*)pAl;
    uint4 vBh = *(const uint4*)pBh;
    uint4 vBl = *(const uint4*)pBl;
    *(uint4*)(sm + woA)          = vAh;
    *(uint4*)(sm + OFF_AL + woA) = vAl;
    *(uint4*)(sm + woB)          = vBh;
    *(uint4*)(sm + BBUF + woB)   = vBl;
    __syncthreads();

    int lr = lane >> 2;
    int lc = (lane & 3) * 4;

    for (int s = 0; s < nst; s++) {
        if (s + 1 < nst) {
            size_t kb = (size_t)(s + 1) * 32;    // 16 bf16 = 32 bytes per stage
            vAh = *(const uint4*)(pAh + kb);
            vAl = *(const uint4*)(pAl + kb);
            vBh = *(const uint4*)(pBh + kb);
            vBl = *(const uint4*)(pBl + kb);
        }

        char* stA = sm + (uint32_t)(s & 1) * STAGEB;
        char* stB = stA + OFF_BH;

        uint32_t ah[2][4], al[2][4], bh[8][2], bl[8][2];
#pragma unroll
        for (int mt = 0; mt < 2; mt++) {
            int rb = (wm * 32 + mt * 16 + lr) * (int)RA + lc;
            ah[mt][0] = *(const uint32_t*)(stA + rb);
            ah[mt][1] = *(const uint32_t*)(stA + rb + 8 * (int)RA);
            ah[mt][2] = *(const uint32_t*)(stA + rb + 16);
            ah[mt][3] = *(const uint32_t*)(stA + rb + 8 * (int)RA + 16);
            al[mt][0] = *(const uint32_t*)(stA + OFF_AL + rb);
            al[mt][1] = *(const uint32_t*)(stA + OFF_AL + rb + 8 * (int)RA);
            al[mt][2] = *(const uint32_t*)(stA + OFF_AL + rb + 16);
            al[mt][3] = *(const uint32_t*)(stA + OFF_AL + rb + 8 * (int)RA + 16);
        }
#pragma unroll
        for (int nt = 0; nt < 8; nt++) {
            int rb = (wn * 64 + nt * 8 + lr) * (int)RB + lc;
            bh[nt][0] = *(const uint32_t*)(stB + rb);
            bh[nt][1] = *(const uint32_t*)(stB + rb + 16);
            bl[nt][0] = *(const uint32_t*)(stB + BBUF + rb);
            bl[nt][1] = *(const uint32_t*)(stB + BBUF + rb + 16);
        }
#pragma unroll
        for (int mt = 0; mt < 2; mt++)
#pragma unroll
            for (int nt = 0; nt < 8; nt++) {
                MMA16816(acc[mt][nt], ah[mt], bh[nt][0], bh[nt][1]);
                MMA16816(acc[mt][nt], al[mt], bh[nt][0], bh[nt][1]);
                MMA16816(acc[mt][nt], ah[mt], bl[nt][0], bl[nt][1]);
            }
        __syncthreads();

        if (s + 1 < nst) {
            char* dst = sm + (uint32_t)((s + 1) & 1) * STAGEB;
            *(uint4*)(dst + woA)          = vAh;
            *(uint4*)(dst + OFF_AL + woA) = vAl;
            *(uint4*)(dst + woB)          = vBh;
            *(uint4*)(dst + BBUF + woB)   = vBl;
        }
        __syncthreads();
    }
}

// ---------------- init / gating / scan ------------------------------------------------
__global__ void init_kernel() {
    int t = threadIdx.x;
    if (t < E_) g_gate_sums[t] = 0.0f;
    if (t == 8) g_bad1 = 0;
    if (t == 9) g_bad2 = 0;
}

__global__ __launch_bounds__(256) void gate_kernel(const float* __restrict__ x,
                                                   const float* __restrict__ wg, int s) {
    __shared__ float swg[M_ * E_];
    __shared__ float bsum[E_];
    int tid = threadIdx.x;
    for (int i = tid; i < M_ * E_; i += 256) swg[i] = wg[i];
    if (tid < E_) bsum[tid] = 0.0f;
    __syncthreads();
    int warp = tid >> 5, lane = tid & 31;
    int tok = blockIdx.x * 8 + warp;
    if (tok < s) {
        const float* xr = x + (size_t)tok * M_;
        float acc[E_];
#pragma unroll
        for (int e = 0; e < E_; e++) acc[e] = 0.0f;
        for (int k = lane; k < M_; k += 32) {
            float xv = xr[k];
#pragma unroll
            for (int e = 0; e < E_; e++) acc[e] += xv * swg[k * E_ + e];
        }
#pragma unroll
        for (int off = 16; off; off >>= 1)
#pragma unroll
            for (int e = 0; e < E_; e++)
                acc[e] += __shfl_down_sync(0xffffffffu, acc[e], off);
        if (lane == 0) {
            float mx = acc[0]; int am = 0;
#pragma unroll
            for (int e = 1; e < E_; e++) if (acc[e] > mx) { mx = acc[e]; am = e; }
            float g[E_]; float sum = 0.0f;
#pragma unroll
            for (int e = 0; e < E_; e++) { g[e] = expf(acc[e] - mx); sum += g[e]; }
            float inv = 1.0f / sum;
            g_idx[tok] = am;
            g_gate[tok] = g[am] * inv;
#pragma unroll
            for (int e = 0; e < E_; e++) atomicAdd(&bsum[e], g[e] * inv);
        }
    }
    __syncthreads();
    if (tid < E_) atomicAdd(&g_gate_sums[tid], bsum[tid]);
}

__global__ __launch_bounds__(256) void scan_kernel(int s, int capacity,
                                                   float* __restrict__ out, long long out_size) {
    __shared__ int cnt[256][E_];
    __shared__ int totals[E_];
    int tid = threadIdx.x;
    int chunk = (s + 255) / 256;
    int lo = tid * chunk, hi = lo + chunk; if (hi > s) hi = s;
    int c[E_];
#pragma unroll
    for (int e = 0; e < E_; e++) c[e] = 0;
    for (int t = lo; t < hi; t++) c[g_idx[t]]++;
#pragma unroll
    for (int e = 0; e < E_; e++) cnt[tid][e] = c[e];
    __syncthreads();
    if (tid < E_) {
        int run = 0;
        for (int i = 0; i < 256; i++) { int v = cnt[i][tid]; cnt[i][tid] = run; run += v; }
        totals[tid] = run;
        g_kept[tid] = run < capacity ? run : capacity;
    }
    __syncthreads();
    int base[E_];
#pragma unroll
    for (int e = 0; e < E_; e++) base[e] = cnt[tid][e];
    for (int t = lo; t < hi; t++) {
        int e = g_idx[t];
        int loc = base[e]++;
        if (loc < capacity) {
            g_slot_token[e * CAP + loc] = t;
            g_slot_gate [e * CAP + loc] = g_gate[t];
        }
    }
    if (tid == 0 && out_size > (long long)s * M_) {
        float la = 0.0f, inv_s = 1.0f / (float)s;
        for (int e = 0; e < E_; e++)
            la += (g_gate_sums[e] * inv_s) * ((float)totals[e] * inv_s);
        la *= (float)E_;
        long long off = (long long)s * M_;
        out[off] = la;
        for (int e = 0; e < E_; e++) out[off + 1 + e] = (float)totals[e];
    }
}

// ---------------- weight transpose + split --------------------------------------------
__global__ __launch_bounds__(256) void transpose_split(const float* __restrict__ in,
                                                       __nv_bfloat16* __restrict__ ohi,
                                                       __nv_bfloat16* __restrict__ olo,
                                                       int R, int C) {
    __shared__ float t[32][33];
    int e = blockIdx.z;
    int c0 = blockIdx.x * 32, r0 = blockIdx.y * 32;
    int tx = threadIdx.x & 31, ty = threadIdx.x >> 5;
    const float* ie = in + (size_t)e * R * C;
#pragma unroll
    for (int i = 0; i < 4; i++)
        t[ty + i * 8][tx] = ie[(size_t)(r0 + ty + i * 8) * C + c0 + tx];
    __syncthreads();
    size_t ob = (size_t)e * C * R;
#pragma unroll
    for (int i = 0; i < 4; i++) {
        int c = c0 + ty + i * 8;
        float v = t[tx][ty + i * 8];
        __nv_bfloat16 h = __float2bfloat16_rn(v);
        size_t o = ob + (size_t)c * R + r0 + tx;
        ohi[o] = h;
        olo[o] = __float2bfloat16_rn(v - __bfloat162float(h));
    }
}

// ---------------- dispatch -------------------------------------------------------------
__global__ __launch_bounds__(256) void dispatch_split(const float* __restrict__ x) {
    int warp = threadIdx.x >> 5, lane = threadIdx.x & 31;
    int row = blockIdx.x * 8 + warp;
    int e = row / CAP, slot = row - e * CAP;
    if (slot >= g_kept[e]) return;
    int t = g_slot_token[row];
    const float* xr = x + (size_t)t * M_;
    __nv_bfloat16* dh = g_disp_hi + (size_t)row * M_;
    __nv_bfloat16* dl = g_disp_lo + (size_t)row * M_;
    for (int k = lane; k < M_; k += 32) {
        float v = xr[k];
        __nv_bfloat16 h = __float2bfloat16_rn(v);
        dh[k] = h;
        dl[k] = __float2bfloat16_rn(v - __bfloat162float(h));
    }
}

// ---------------- gemm1 epilogue helper: gelu -> fp32 + bf16 split --------------------
__device__ __forceinline__ void h_store(float v0, float v1, size_t off) {
    float u0 = 0.7978845608028654f * (v0 + 0.044715f * v0 * v0 * v0);
    float u1 = 0.7978845608028654f * (v1 + 0.044715f * v1 * v1 * v1);
    float g0 = 0.5f * v0 * (1.0f + tanhf(u0));
    float g1 = 0.5f * v1 * (1.0f + tanhf(u1));
    __nv_bfloat16 h0 = __float2bfloat16_rn(g0);
    __nv_bfloat16 h1 = __float2bfloat16_rn(g1);
    __nv_bfloat162 hp = __halves2bfloat162(h0, h1);
    __nv_bfloat162 lp = __halves2bfloat162(
        __float2bfloat16_rn(g0 - __bfloat162float(h0)),
        __float2bfloat16_rn(g1 - __bfloat162float(h1)));
    *(uint32_t*)(g_h_hi + off) = *(uint32_t*)&hp;
    *(uint32_t*)(g_h_lo + off) = *(uint32_t*)&lp;
    *(float2*)(g_h + off) = make_float2(g0, g1);
}

// ---------------- gemm1 mma (all experts) ----------------------------------------------
__global__ __launch_bounds__(256) void gemm1_mma(const float* __restrict__ b1) {
    int e = blockIdx.z;
    int kept = g_kept[e];
    int m0 = blockIdx.y * 128;
    if (m0 >= kept) return;
    int n0 = blockIdx.x * 128;
    extern __shared__ char sm[];
    int tid = threadIdx.x;

    float acc[2][8][4];
#pragma unroll
    for (int i = 0; i < 2; i++)
#pragma unroll
        for (int j = 0; j < 8; j++)
#pragma unroll
            for (int k = 0; k < 4; k++) acc[i][j][k] = 0.0f;

    mma_mainloop(g_disp_hi, g_disp_lo, g_w1t_hi, g_w1t_lo,
                 (size_t)e * CAP + m0, (size_t)e * H_ + n0, M_, sm, tid, acc);

    int wid = tid >> 5, lane = tid & 31, wm = wid & 3, wn = wid >> 2;
    const float2* b1e = (const float2*)(b1 + (size_t)e * H_);
    size_t rowbase = (size_t)e * CAP;
#pragma unroll
    for (int mt = 0; mt < 2; mt++) {
        int r0 = m0 + wm * 32 + mt * 16 + (lane >> 2);
        int r1 = r0 + 8;
#pragma unroll
        for (int nt = 0; nt < 8; nt++) {
            int col = n0 + wn * 64 + nt * 8 + (lane & 3) * 2;
            float2 bb = b1e[col >> 1];
            if (r0 < kept)
                h_store(acc[mt][nt][0] + bb.x, acc[mt][nt][1] + bb.y,
                        (rowbase + r0) * H_ + col);
            if (r1 < kept)
                h_store(acc[mt][nt][2] + bb.x, acc[mt][nt][3] + bb.y,
                        (rowbase + r1) * H_ + col);
        }
    }
}

// ---------------- check1: sparse fp32 reference vs mma h ------------------------------
__global__ __launch_bounds__(256) void check1_kernel(const float* __restrict__ x,
                                                     const float* __restrict__ w1,
                                                     const float* __restrict__ b1) {
    int e = blockIdx.x >> 8;
    int kept = g_kept[e];
    if (kept <= 0) return;
    int warp = threadIdx.x >> 5, lane = threadIdx.x & 31;
    int i = ((blockIdx.x & 255) << 3) + warp;
    int r = (i * 179 + 7) % kept;
    int n = (i * 613 + 31) % H_;
    int t = g_slot_token[e * CAP + r];
    const float* xr = x + (size_t)t * M_;
    const float* wc = w1 + (size_t)e * M_ * H_ + n;
    float acc = 0.0f;
    for (int k = lane; k < M_; k += 32) acc += xr[k] * wc[(size_t)k * H_];
#pragma unroll
    for (int o = 16; o; o >>= 1) acc += __shfl_down_sync(0xffffffffu, acc, o);
    if (lane == 0) {
        float v = acc + b1[e * H_ + n];
        float u = 0.7978845608028654f * (v + 0.044715f * v * v * v);
        float ref = 0.5f * v * (1.0f + tanhf(u));
        float got = g_h[((size_t)e * CAP + r) * H_ + n];
        if (fabsf(got - ref) > 1e-3f * (fabsf(ref) + 1.0f)) atomicOr(&g_bad1, 1);
    }
}

// ---------------- gemm1 simt repair (runs only if g_bad1) ------------------------------
__global__ __launch_bounds__(256) void gemm1_simt(const float* __restrict__ x,
                                                  const float* __restrict__ w1,
                                                  const float* __restrict__ b1) {
    if (g_bad1 == 0) return;
    const int e = blockIdx.z;
    const int kept = g_kept[e];
    const int m0 = blockIdx.y * 128;
    if (m0 >= kept) return;
    const int n0 = blockIdx.x * 128;

    __shared__ float As[16][128];
    __shared__ float Bs[16][128];
    __shared__ int   tok[128];

    int tid = threadIdx.x;
    if (tid < 128) {
        int r = m0 + tid;
        tok[tid] = (r < kept) ? g_slot_token[e * CAP + r] : -1;
    }
    __syncthreads();

    const float* w1e = w1 + (size_t)e * M_ * H_;
    float acc[8][8];
#pragma unroll
    for (int i = 0; i < 8; i++)
#pragma unroll
        for (int j = 0; j < 8; j++) acc[i][j] = 0.0f;

    int tx = tid & 15, ty = tid >> 4;
    for (int k0 = 0; k0 < M_; k0 += 16) {
#pragma unroll
        for (int i = 0; i < 2; i++) {
            int slot = tid + i * 256;
            int row = slot >> 2, kk = (slot & 3) * 4;
            float4 v = make_float4(0.f, 0.f, 0.f, 0.f);
            int t = tok[row];
            if (t >= 0) v = *(const float4*)(x + (size_t)t * M_ + k0 + kk);
            As[kk + 0][row] = v.x; As[kk + 1][row] = v.y;
            As[kk + 2][row] = v.z; As[kk + 3][row] = v.w;
        }
#pragma unroll
        for (int i = 0; i < 2; i++) {
            int slot = tid + i * 256;
            int bk = slot >> 5, bn = (slot & 31) * 4;
            *(float4*)&Bs[bk][bn] = *(const float4*)(w1e + (size_t)(k0 + bk) * H_ + n0 + bn);
        }
        __syncthreads();
#pragma unroll
        for (int kk = 0; kk < 16; kk++) {
            float a[8], b[8];
#pragma unroll
            for (int i = 0; i < 8; i++) a[i] = As[kk][ty * 8 + i];
#pragma unroll
            for (int j = 0; j < 8; j++) b[j] = Bs[kk][tx * 8 + j];
#pragma unroll
            for (int i = 0; i < 8; i++)
#pragma unroll
                for (int j = 0; j < 8; j++) acc[i][j] += a[i] * b[j];
        }
        __syncthreads();
    }

    const float* b1e = b1 + e * H_;
#pragma unroll
    for (int i = 0; i < 8; i++) {
        int r = m0 + ty * 8 + i;
        if (r < kept) {
            float* hrow = g_h + ((size_t)e * CAP + r) * H_;
#pragma unroll
            for (int j = 0; j < 8; j++) {
                int n = n0 + tx * 8 + j;
                float v = acc[i][j] + b1e[n];
                float u = 0.7978845608028654f * (v + 0.044715f * v * v * v);
                hrow[n] = 0.5f * v * (1.0f + tanhf(u));
            }
        }
    }
}

// ---------------- gemm2 mma (skipped if gemm1 was bad) ---------------------------------
__global__ __launch_bounds__(256) void gemm2_mma(const float* __restrict__ b2,
                                                 float* __restrict__ out) {
    if (g_bad1 != 0) return;
    int e = blockIdx.z;
    int kept = g_kept[e];
    int m0 = blockIdx.y * 128;
    if (m0 >= kept) return;
    int n0 = blockIdx.x * 128;
    extern __shared__ char sm[];
    int tid = threadIdx.x;

    float acc[2][8][4];
#pragma unroll
    for (int i = 0; i < 2; i++)
#pragma unroll
        for (int j = 0; j < 8; j++)
#pragma unroll
            for (int k = 0; k < 4; k++) acc[i][j][k] = 0.0f;

    mma_mainloop(g_h_hi, g_h_lo, g_w2t_hi, g_w2t_lo,
                 (size_t)e * CAP + m0, (size_t)e * M_ + n0, H_, sm, tid, acc);

    int wid = tid >> 5, lane = tid & 31, wm = wid & 3, wn = wid >> 2;
    const float2* b2e = (const float2*)(b2 + (size_t)e * M_);
#pragma unroll
    for (int mt = 0; mt < 2; mt++) {
        int r0 = m0 + wm * 32 + mt * 16 + (lane >> 2);
        int r1 = r0 + 8;
        int t0 = (r0 < kept) ? g_slot_token[e * CAP + r0] : -1;
        int t1 = (r1 < kept) ? g_slot_token[e * CAP + r1] : -1;
        float ga0 = (r0 < kept) ? g_slot_gate[e * CAP + r0] : 0.0f;
        float ga1 = (r1 < kept) ? g_slot_gate[e * CAP + r1] : 0.0f;
#pragma unroll
        for (int nt = 0; nt < 8; nt++) {
            int col = n0 + wn * 64 + nt * 8 + (lane & 3) * 2;
            float2 bb = b2e[col >> 1];
            if (t0 >= 0)
                *(float2*)(out + (size_t)t0 * M_ + col) =
                    make_float2((acc[mt][nt][0] + bb.x) * ga0,
                                (acc[mt][nt][1] + bb.y) * ga0);
            if (t1 >= 0)
                *(float2*)(out + (size_t)t1 * M_ + col) =
                    make_float2((acc[mt][nt][2] + bb.x) * ga1,
                                (acc[mt][nt][3] + bb.y) * ga1);
        }
    }
}

// ---------------- check2: sparse reference vs out ---------------------------------------
__global__ __launch_bounds__(256) void check2_kernel(const float* __restrict__ w2,
                                                     const float* __restrict__ b2,
                                                     const float* __restrict__ out) {
    int e = blockIdx.x >> 7;
    int kept = g_kept[e];
    if (kept <= 0) return;
    int warp = threadIdx.x >> 5, lane = threadIdx.x & 31;
    int i = ((blockIdx.x & 127) << 3) + warp;
    int r = (i * 241 + 3) % kept;
    int n = (i * 97 + 5) % M_;
    int t = g_slot_token[e * CAP + r];
    float gate = g_slot_gate[e * CAP + r];
    const float* hr = g_h + ((size_t)e * CAP + r) * H_;
    const float* wc = w2 + (size_t)e * H_ * M_ + n;
    float acc = 0.0f;
    for (int k = lane; k < H_; k += 32) acc += hr[k] * wc[(size_t)k * M_];
#pragma unroll
    for (int o = 16; o; o >>= 1) acc += __shfl_down_sync(0xffffffffu, acc, o);
    if (lane == 0) {
        float ref = (acc + b2[e * M_ + n]) * gate;
        float got = out[(size_t)t * M_ + n];
        if (fabsf(got - ref) > 1e-3f * (fabsf(ref) + 1.0f)) atomicOr(&g_bad2, 1);
    }
}

// ---------------- gemm2 simt repair (runs only if g_bad2) -------------------------------
__global__ __launch_bounds__(256) void gemm2_simt(const float* __restrict__ w2,
                                                  const float* __restrict__ b2,
                                                  float* __restrict__ out) {
    if (g_bad2 == 0) return;
    const int e = blockIdx.z;
    const int kept = g_kept[e];
    const int m0 = blockIdx.y * 128;
    if (m0 >= kept) return;
    const int n0 = blockIdx.x * 128;

    __shared__ float As[16][128];
    __shared__ float Bs[16][128];

    int tid = threadIdx.x;
    const float* w2e  = w2 + (size_t)e * H_ * M_;
    const float* hblk = g_h + ((size_t)e * CAP + m0) * H_;

    float acc[8][8];
#pragma unroll
    for (int i = 0; i < 8; i++)
#pragma unroll
        for (int j = 0; j < 8; j++) acc[i][j] = 0.0f;

    int tx = tid & 15, ty = tid >> 4;
    for (int k0 = 0; k0 < H_; k0 += 16) {
#pragma unroll
        for (int i = 0; i < 2; i++) {
            int slot = tid + i * 256;
            int row = slot >> 2, kk = (slot & 3) * 4;
            float4 v = *(const float4*)(hblk + (size_t)row * H_ + k0 + kk);
            As[kk + 0][row] = v.x; As[kk + 1][row] = v.y;
            As[kk + 2][row] = v.z; As[kk + 3][row] = v.w;
        }
#pragma unroll
        for (int i = 0; i < 2; i++) {
            int slot = tid + i * 256;
            int bk = slot >> 5, bn = (slot & 31) * 4;
            *(float4*)&Bs[bk][bn] = *(const float4*)(w2e + (size_t)(k0 + bk) * M_ + n0 + bn);
        }
        __syncthreads();
#pragma unroll
        for (int kk = 0; kk < 16; kk++) {
            float a[8], b[8];
#pragma unroll
            for (int i = 0; i < 8; i++) a[i] = As[kk][ty * 8 + i];
#pragma unroll
            for (int j = 0; j < 8; j++) b[j] = Bs[kk][tx * 8 + j];
#pragma unroll
            for (int i = 0; i < 8; i++)
#pragma unroll
                for (int j = 0; j < 8; j++) acc[i][j] += a[i] * b[j];
        }
        __syncthreads();
    }

    const float* b2e = b2 + e * M_;
#pragma unroll
    for (int i = 0; i < 8; i++) {
        int r = m0 + ty * 8 + i;
        if (r < kept) {
            int t = g_slot_token[e * CAP + r];
            float gate = g_slot_gate[e * CAP + r];
            float* orow = out + (size_t)t * M_;
#pragma unroll
            for (int j = 0; j < 8; j++) {
                int n = n0 + tx * 8 + j;
                orow[n] = (acc[i][j] + b2e[n]) * gate;
            }
        }
    }
}

// ---------------- launch -----------------------------------------------------------------
extern "C" void kernel_launch(void* const* d_in, const int* in_sizes, int n_in,
                              void* d_out, int out_size) {
    const float* x  = (const float*)d_in[0];
    const float* wg = (const float*)d_in[1];
    const float* w1 = (const float*)d_in[2];
    const float* b1 = (const float*)d_in[3];
    const float* w2 = (const float*)d_in[4];
    const float* b2 = (const float*)d_in[5];
    float* out = (float*)d_out;

    int s = in_sizes[0] / M_;
    int capacity = (s + E_ - 1) / E_;
    if (capacity < 4) capacity = 4;
    if (capacity > CAP) capacity = CAP;

    cudaMemsetAsync(d_out, 0, (size_t)out_size * sizeof(float), 0);

    init_kernel<<<1, 32>>>();
    gate_kernel<<<(s + 7) / 8, 256>>>(x, wg, s);
    scan_kernel<<<1, 256>>>(s, capacity, out, (long long)out_size);

    dim3 tg1(H_ / 32, M_ / 32, E_);
    transpose_split<<<tg1, 256>>>(w1, g_w1t_hi, g_w1t_lo, M_, H_);
    dim3 tg2(M_ / 32, H_ / 32, E_);
    transpose_split<<<tg2, 256>>>(w2, g_w2t_hi, g_w2t_lo, H_, M_);

    dispatch_split<<<E_ * CAP / 8, 256>>>(x);

    dim3 g1(H_ / 128, CAP / 128, E_);
    gemm1_mma<<<g1, 256, SMEM_MMA>>>(b1);
    check1_kernel<<<2048, 256>>>(x, w1, b1);
    gemm1_simt<<<g1, 256>>>(x, w1, b1);

    dim3 g2(M_ / 128, CAP / 128, E_);
    gemm2_mma<<<g2, 256, SMEM_MMA>>>(b2, out);
    check2_kernel<<<1024, 256>>>(w2, b2, out);
    gemm2_simt<<<g2, 256>>>(w2, b2, out);
}

// round 10
// speedup vs baseline: 1.6534x; 1.6534x over previous
#include <cuda_runtime.h>
#include <cuda_bf16.h>
#include <stdint.h>
#include <math.h>

#define E_   8
#define M_   1024
#define H_   4096
#define SMAX 16384
#define CAP  2048

// ---------------- device scratch ------------------------------------------------
__device__ int   g_idx[SMAX];
__device__ float g_gate[SMAX];
__device__ float g_gate_sums[E_];
__device__ int   g_kept[E_];
__device__ int   g_slot_token[E_ * CAP];
__device__ float g_slot_gate[E_ * CAP];
__device__ float g_h[(size_t)E_ * CAP * H_];   // fp32 intermediate activations

// packed f32x2 FMA: both lanes of the b64 regs are fp32; elementwise d = a*b + d
#define FMA2(c, a, b) \
    asm("fma.rn.f32x2 %0, %1, %2, %0;" : "+l"(c) : "l"(a), "l"(b))

// ---------------- init ----------------------------------------------------------
__global__ void init_kernel() {
    if (threadIdx.x < E_) g_gate_sums[threadIdx.x] = 0.0f;
}

// ---------------- gating (validated R1) ------------------------------------------
__global__ __launch_bounds__(256) void gate_kernel(const float* __restrict__ x,
                                                   const float* __restrict__ wg, int s) {
    __shared__ float swg[M_ * E_];
    __shared__ float bsum[E_];
    int tid = threadIdx.x;
    for (int i = tid; i < M_ * E_; i += 256) swg[i] = wg[i];
    if (tid < E_) bsum[tid] = 0.0f;
    __syncthreads();
    int warp = tid >> 5, lane = tid & 31;
    int tok = blockIdx.x * 8 + warp;
    if (tok < s) {
        const float* xr = x + (size_t)tok * M_;
        float acc[E_];
#pragma unroll
        for (int e = 0; e < E_; e++) acc[e] = 0.0f;
        for (int k = lane; k < M_; k += 32) {
            float xv = xr[k];
#pragma unroll
            for (int e = 0; e < E_; e++) acc[e] += xv * swg[k * E_ + e];
        }
#pragma unroll
        for (int off = 16; off; off >>= 1)
#pragma unroll
            for (int e = 0; e < E_; e++)
                acc[e] += __shfl_down_sync(0xffffffffu, acc[e], off);
        if (lane == 0) {
            float mx = acc[0]; int am = 0;
#pragma unroll
            for (int e = 1; e < E_; e++) if (acc[e] > mx) { mx = acc[e]; am = e; }
            float g[E_]; float sum = 0.0f;
#pragma unroll
            for (int e = 0; e < E_; e++) { g[e] = expf(acc[e] - mx); sum += g[e]; }
            float inv = 1.0f / sum;
            g_idx[tok]  = am;
            g_gate[tok] = g[am] * inv;
#pragma unroll
            for (int e = 0; e < E_; e++) atomicAdd(&bsum[e], g[e] * inv);
        }
    }
    __syncthreads();
    if (tid < E_) atomicAdd(&g_gate_sums[tid], bsum[tid]);
}

// ---------------- routing scan (validated R1) -------------------------------------
__global__ __launch_bounds__(256) void scan_kernel(int s, int capacity,
                                                   float* __restrict__ out, long long out_size) {
    __shared__ int cnt[256][E_];
    __shared__ int totals[E_];
    int tid = threadIdx.x;
    int chunk = (s + 255) / 256;
    int lo = tid * chunk, hi = lo + chunk; if (hi > s) hi = s;
    int c[E_];
#pragma unroll
    for (int e = 0; e < E_; e++) c[e] = 0;
    for (int t = lo; t < hi; t++) c[g_idx[t]]++;
#pragma unroll
    for (int e = 0; e < E_; e++) cnt[tid][e] = c[e];
    __syncthreads();
    if (tid < E_) {
        int run = 0;
        for (int i = 0; i < 256; i++) { int v = cnt[i][tid]; cnt[i][tid] = run; run += v; }
        totals[tid] = run;
        g_kept[tid] = run < capacity ? run : capacity;
    }
    __syncthreads();
    int base[E_];
#pragma unroll
    for (int e = 0; e < E_; e++) base[e] = cnt[tid][e];
    for (int t = lo; t < hi; t++) {
        int e = g_idx[t];
        int loc = base[e]++;
        if (loc < capacity) {
            g_slot_token[e * CAP + loc] = t;
            g_slot_gate [e * CAP + loc] = g_gate[t];
        }
    }
    if (tid == 0 && out_size > (long long)s * M_) {
        float la = 0.0f, inv_s = 1.0f / (float)s;
        for (int e = 0; e < E_; e++)
            la += (g_gate_sums[e] * inv_s) * ((float)totals[e] * inv_s);
        la *= (float)E_;
        long long off = (long long)s * M_;
        out[off] = la;
        for (int e = 0; e < E_; e++) out[off + 1 + e] = (float)totals[e];
    }
}

// ---------------- GEMM1: h = gelu(gather(x) @ w1[e] + b1[e]), f32x2 inner ---------
// A staged DUPLICATED ({v,v}) so ulonglong2 LDS yields packed broadcast operands.
__global__ __launch_bounds__(256) void gemm1_kernel(const float* __restrict__ x,
                                                    const float* __restrict__ w1,
                                                    const float* __restrict__ b1,
                                                    int capacity) {
    const int e = blockIdx.z;
    const int kept = g_kept[e];
    const int m0 = blockIdx.y * 128;
    if (m0 >= kept) return;
    const int n0 = blockIdx.x * 128;

    __shared__ float As2[16][260];     // duplicated: [k][2*row+{0,1}] = a(row,k)
    __shared__ float Bs[16][128];
    __shared__ int   tok[128];

    int tid = threadIdx.x;
    if (tid < 128) {
        int r = m0 + tid;
        tok[tid] = (r < kept) ? g_slot_token[e * capacity + r] : -1;
    }
    __syncthreads();

    const float* w1e = w1 + (size_t)e * M_ * H_;
    unsigned long long acc2[8][4];
#pragma unroll
    for (int i = 0; i < 8; i++)
#pragma unroll
        for (int j = 0; j < 4; j++) acc2[i][j] = 0ull;   // {0.f, 0.f}

    int tx = tid & 15;   // N direction (8 cols = 4 pairs)
    int ty = tid >> 4;   // M direction (8 rows)

    for (int k0 = 0; k0 < M_; k0 += 16) {
#pragma unroll
        for (int i = 0; i < 2; i++) {
            int slot = tid + i * 256;          // 512 slots = 128 rows x 4
            int row = slot >> 2;
            int kk  = (slot & 3) * 4;
            float4 v = make_float4(0.f, 0.f, 0.f, 0.f);
            int t = tok[row];
            if (t >= 0) v = *(const float4*)(x + (size_t)t * M_ + k0 + kk);
            *(float2*)&As2[kk + 0][2 * row] = make_float2(v.x, v.x);
            *(float2*)&As2[kk + 1][2 * row] = make_float2(v.y, v.y);
            *(float2*)&As2[kk + 2][2 * row] = make_float2(v.z, v.z);
            *(float2*)&As2[kk + 3][2 * row] = make_float2(v.w, v.w);
        }
#pragma unroll
        for (int i = 0; i < 2; i++) {
            int slot = tid + i * 256;          // 512 slots = 16 k x 32
            int bk = slot >> 5;
            int bn = (slot & 31) * 4;
            *(float4*)&Bs[bk][bn] =
                *(const float4*)(w1e + (size_t)(k0 + bk) * H_ + n0 + bn);
        }
        __syncthreads();
#pragma unroll
        for (int kk = 0; kk < 16; kk++) {
            unsigned long long aa[8], bb[4];
#pragma unroll
            for (int ii = 0; ii < 4; ii++) {
                ulonglong2 t2 = *(const ulonglong2*)&As2[kk][(ty * 8 + ii * 2) * 2];
                aa[ii * 2]     = t2.x;
                aa[ii * 2 + 1] = t2.y;
            }
            {
                ulonglong2 b01 = *(const ulonglong2*)&Bs[kk][tx * 8];
                ulonglong2 b23 = *(const ulonglong2*)&Bs[kk][tx * 8 + 4];
                bb[0] = b01.x; bb[1] = b01.y; bb[2] = b23.x; bb[3] = b23.y;
            }
#pragma unroll
            for (int i = 0; i < 8; i++)
#pragma unroll
                for (int j = 0; j < 4; j++)
                    FMA2(acc2[i][j], aa[i], bb[j]);
        }
        __syncthreads();
    }

    const float* b1e = b1 + e * H_;
#pragma unroll
    for (int i = 0; i < 8; i++) {
        int r = m0 + ty * 8 + i;
        if (r < kept) {
            float* hrow = g_h + ((size_t)e * CAP + r) * H_;
#pragma unroll
            for (int j = 0; j < 4; j++) {
                int n = n0 + tx * 8 + j * 2;
                float p0 = __uint_as_float((uint32_t)acc2[i][j]);
                float p1 = __uint_as_float((uint32_t)(acc2[i][j] >> 32));
                float v0 = p0 + b1e[n];
                float v1 = p1 + b1e[n + 1];
                float u0 = 0.7978845608028654f * (v0 + 0.044715f * v0 * v0 * v0);
                float u1 = 0.7978845608028654f * (v1 + 0.044715f * v1 * v1 * v1);
                hrow[n]     = 0.5f * v0 * (1.0f + tanhf(u0));
                hrow[n + 1] = 0.5f * v1 * (1.0f + tanhf(u1));
            }
        }
    }
}

// ---------------- GEMM2: out[token] = (h @ w2[e] + b2[e]) * gate, f32x2 inner ------
__global__ __launch_bounds__(256) void gemm2_kernel(const float* __restrict__ w2,
                                                    const float* __restrict__ b2,
                                                    float* __restrict__ out,
                                                    int capacity) {
    const int e = blockIdx.z;
    const int kept = g_kept[e];
    const int m0 = blockIdx.y * 128;
    if (m0 >= kept) return;
    const int n0 = blockIdx.x * 128;

    __shared__ float As2[16][260];
    __shared__ float Bs[16][128];

    int tid = threadIdx.x;
    const float* w2e  = w2 + (size_t)e * H_ * M_;
    const float* hblk = g_h + ((size_t)e * CAP + m0) * H_;

    unsigned long long acc2[8][4];
#pragma unroll
    for (int i = 0; i < 8; i++)
#pragma unroll
        for (int j = 0; j < 4; j++) acc2[i][j] = 0ull;

    int tx = tid & 15;
    int ty = tid >> 4;

    for (int k0 = 0; k0 < H_; k0 += 16) {
#pragma unroll
        for (int i = 0; i < 2; i++) {
            int slot = tid + i * 256;
            int row = slot >> 2;
            int kk  = (slot & 3) * 4;
            // rows >= kept read stale scratch; results for them are never stored
            float4 v = *(const float4*)(hblk + (size_t)row * H_ + k0 + kk);
            *(float2*)&As2[kk + 0][2 * row] = make_float2(v.x, v.x);
            *(float2*)&As2[kk + 1][2 * row] = make_float2(v.y, v.y);
            *(float2*)&As2[kk + 2][2 * row] = make_float2(v.z, v.z);
            *(float2*)&As2[kk + 3][2 * row] = make_float2(v.w, v.w);
        }
#pragma unroll
        for (int i = 0; i < 2; i++) {
            int slot = tid + i * 256;
            int bk = slot >> 5;
            int bn = (slot & 31) * 4;
            *(float4*)&Bs[bk][bn] =
                *(const float4*)(w2e + (size_t)(k0 + bk) * M_ + n0 + bn);
        }
        __syncthreads();
#pragma unroll
        for (int kk = 0; kk < 16; kk++) {
            unsigned long long aa[8], bb[4];
#pragma unroll
            for (int ii = 0; ii < 4; ii++) {
                ulonglong2 t2 = *(const ulonglong2*)&As2[kk][(ty * 8 + ii * 2) * 2];
                aa[ii * 2]     = t2.x;
                aa[ii * 2 + 1] = t2.y;
            }
            {
                ulonglong2 b01 = *(const ulonglong2*)&Bs[kk][tx * 8];
                ulonglong2 b23 = *(const ulonglong2*)&Bs[kk][tx * 8 + 4];
                bb[0] = b01.x; bb[1] = b01.y; bb[2] = b23.x; bb[3] = b23.y;
            }
#pragma unroll
            for (int i = 0; i < 8; i++)
#pragma unroll
                for (int j = 0; j < 4; j++)
                    FMA2(acc2[i][j], aa[i], bb[j]);
        }
        __syncthreads();
    }

    const float* b2e = b2 + e * M_;
#pragma unroll
    for (int i = 0; i < 8; i++) {
        int r = m0 + ty * 8 + i;
        if (r < kept) {
            int t = g_slot_token[e * capacity + r];
            float gate = g_slot_gate[e * capacity + r];
            float* orow = out + (size_t)t * M_;
#pragma unroll
            for (int j = 0; j < 4; j++) {
                int n = n0 + tx * 8 + j * 2;
                float p0 = __uint_as_float((uint32_t)acc2[i][j]);
                float p1 = __uint_as_float((uint32_t)(acc2[i][j] >> 32));
                orow[n]     = (p0 + b2e[n])     * gate;
                orow[n + 1] = (p1 + b2e[n + 1]) * gate;
            }
        }
    }
}

// ---------------- launch -------------------------------------------------------
extern "C" void kernel_launch(void* const* d_in, const int* in_sizes, int n_in,
                              void* d_out, int out_size) {
    const float* x  = (const float*)d_in[0];
    const float* wg = (const float*)d_in[1];
    const float* w1 = (const float*)d_in[2];
    const float* b1 = (const float*)d_in[3];
    const float* w2 = (const float*)d_in[4];
    const float* b2 = (const float*)d_in[5];
    float* out = (float*)d_out;

    int s = in_sizes[0] / M_;
    int capacity = (s + E_ - 1) / E_;
    if (capacity < 4) capacity = 4;
    if (capacity > CAP) capacity = CAP;

    cudaMemsetAsync(d_out, 0, (size_t)out_size * sizeof(float), 0);

    init_kernel<<<1, 32>>>();
    gate_kernel<<<(s + 7) / 8, 256>>>(x, wg, s);
    scan_kernel<<<1, 256>>>(s, capacity, out, (long long)out_size);

    dim3 g1(H_ / 128, (capacity + 127) / 128, E_);
    gemm1_kernel<<<g1, 256>>>(x, w1, b1, capacity);

    dim3 g2(M_ / 128, (capacity + 127) / 128, E_);
    gemm2_kernel<<<g2, 256>>>(w2, b2, out, capacity);
}

// round 11
// speedup vs baseline: 2.2725x; 1.3745x over previous
#include <cuda_runtime.h>
#include <cuda_bf16.h>
#include <stdint.h>
#include <math.h>

#define E_   8
#define M_   1024
#define H_   4096
#define SMAX 16384
#define CAP  2048

// ---------------- device scratch ------------------------------------------------
__device__ int   g_idx[SMAX];
__device__ float g_gate[SMAX];
__device__ float g_gate_sums[E_];
__device__ int   g_kept[E_];
__device__ int   g_slot_token[E_ * CAP];
__device__ float g_slot_gate[E_ * CAP];
__device__ float g_h[(size_t)E_ * CAP * H_];   // fp32 intermediate activations

typedef unsigned long long u64;

// packed f32x2 FMA: elementwise d = a*b + d on both fp32 lanes
#define FMA2(c, a, b) \
    asm("fma.rn.f32x2 %0, %1, %2, %0;" : "+l"(c) : "l"(a), "l"(b))
// duplicate one fp32 into both lanes of a b64
#define DUP2(d, v) \
    asm("mov.b64 %0, {%1, %1};" : "=l"(d) : "f"(v))

// ---------------- init ----------------------------------------------------------
__global__ void init_kernel() {
    if (threadIdx.x < E_) g_gate_sums[threadIdx.x] = 0.0f;
}

// ---------------- gating (validated R1) ------------------------------------------
__global__ __launch_bounds__(256) void gate_kernel(const float* __restrict__ x,
                                                   const float* __restrict__ wg, int s) {
    __shared__ float swg[M_ * E_];
    __shared__ float bsum[E_];
    int tid = threadIdx.x;
    for (int i = tid; i < M_ * E_; i += 256) swg[i] = wg[i];
    if (tid < E_) bsum[tid] = 0.0f;
    __syncthreads();
    int warp = tid >> 5, lane = tid & 31;
    int tok = blockIdx.x * 8 + warp;
    if (tok < s) {
        const float* xr = x + (size_t)tok * M_;
        float acc[E_];
#pragma unroll
        for (int e = 0; e < E_; e++) acc[e] = 0.0f;
        for (int k = lane; k < M_; k += 32) {
            float xv = xr[k];
#pragma unroll
            for (int e = 0; e < E_; e++) acc[e] += xv * swg[k * E_ + e];
        }
#pragma unroll
        for (int off = 16; off; off >>= 1)
#pragma unroll
            for (int e = 0; e < E_; e++)
                acc[e] += __shfl_down_sync(0xffffffffu, acc[e], off);
        if (lane == 0) {
            float mx = acc[0]; int am = 0;
#pragma unroll
            for (int e = 1; e < E_; e++) if (acc[e] > mx) { mx = acc[e]; am = e; }
            float g[E_]; float sum = 0.0f;
#pragma unroll
            for (int e = 0; e < E_; e++) { g[e] = expf(acc[e] - mx); sum += g[e]; }
            float inv = 1.0f / sum;
            g_idx[tok]  = am;
            g_gate[tok] = g[am] * inv;
#pragma unroll
            for (int e = 0; e < E_; e++) atomicAdd(&bsum[e], g[e] * inv);
        }
    }
    __syncthreads();
    if (tid < E_) atomicAdd(&g_gate_sums[tid], bsum[tid]);
}

// ---------------- routing scan (validated R1) -------------------------------------
__global__ __launch_bounds__(256) void scan_kernel(int s, int capacity,
                                                   float* __restrict__ out, long long out_size) {
    __shared__ int cnt[256][E_];
    __shared__ int totals[E_];
    int tid = threadIdx.x;
    int chunk = (s + 255) / 256;
    int lo = tid * chunk, hi = lo + chunk; if (hi > s) hi = s;
    int c[E_];
#pragma unroll
    for (int e = 0; e < E_; e++) c[e] = 0;
    for (int t = lo; t < hi; t++) c[g_idx[t]]++;
#pragma unroll
    for (int e = 0; e < E_; e++) cnt[tid][e] = c[e];
    __syncthreads();
    if (tid < E_) {
        int run = 0;
        for (int i = 0; i < 256; i++) { int v = cnt[i][tid]; cnt[i][tid] = run; run += v; }
        totals[tid] = run;
        g_kept[tid] = run < capacity ? run : capacity;
    }
    __syncthreads();
    int base[E_];
#pragma unroll
    for (int e = 0; e < E_; e++) base[e] = cnt[tid][e];
    for (int t = lo; t < hi; t++) {
        int e = g_idx[t];
        int loc = base[e]++;
        if (loc < capacity) {
            g_slot_token[e * CAP + loc] = t;
            g_slot_gate [e * CAP + loc] = g_gate[t];
        }
    }
    if (tid == 0 && out_size > (long long)s * M_) {
        float la = 0.0f, inv_s = 1.0f / (float)s;
        for (int e = 0; e < E_; e++)
            la += (g_gate_sums[e] * inv_s) * ((float)totals[e] * inv_s);
        la *= (float)E_;
        long long off = (long long)s * M_;
        out[off] = la;
        for (int e = 0; e < E_; e++) out[off + 1 + e] = (float)totals[e];
    }
}

// ---------------- shared GEMM inner: 128x128 tile, FMA2, conflict-free --------------
// As/Bs: [16][132] fp32, row-major per k-slice. Per-thread quads:
//   rows ty*4+{0..3} and 64+ty*4+{0..3}; cols tx*4+{0..3} and 64+tx*4+{0..3}.
#define SROW 132

__device__ __forceinline__ void inner_tile(const float (*As)[SROW],
                                           const float (*Bs)[SROW],
                                           int tx, int ty, u64 acc2[8][4]) {
#pragma unroll
    for (int kk = 0; kk < 16; kk++) {
        float4 a0 = *(const float4*)&As[kk][ty * 4];
        float4 a1 = *(const float4*)&As[kk][64 + ty * 4];
        float4 b0 = *(const float4*)&Bs[kk][tx * 4];
        float4 b1 = *(const float4*)&Bs[kk][64 + tx * 4];
        u64 aa[8], bb[4];
        DUP2(aa[0], a0.x); DUP2(aa[1], a0.y); DUP2(aa[2], a0.z); DUP2(aa[3], a0.w);
        DUP2(aa[4], a1.x); DUP2(aa[5], a1.y); DUP2(aa[6], a1.z); DUP2(aa[7], a1.w);
        bb[0] = ((const u64*)&b0)[0]; bb[1] = ((const u64*)&b0)[1];
        bb[2] = ((const u64*)&b1)[0]; bb[3] = ((const u64*)&b1)[1];
#pragma unroll
        for (int i = 0; i < 8; i++)
#pragma unroll
            for (int j = 0; j < 4; j++)
                FMA2(acc2[i][j], aa[i], bb[j]);
    }
}

// ---------------- GEMM1: h = gelu(gather(x) @ w1[e] + b1[e]) -----------------------
__global__ __launch_bounds__(256) void gemm1_kernel(const float* __restrict__ x,
                                                    const float* __restrict__ w1,
                                                    const float* __restrict__ b1,
                                                    int capacity) {
    const int e = blockIdx.z;
    const int kept = g_kept[e];
    const int m0 = blockIdx.y * 128;
    if (m0 >= kept) return;
    const int n0 = blockIdx.x * 128;

    __shared__ float As[16][SROW];
    __shared__ float Bs[16][SROW];
    __shared__ int   tok[128];

    int tid = threadIdx.x;
    if (tid < 128) {
        int r = m0 + tid;
        tok[tid] = (r < kept) ? g_slot_token[e * capacity + r] : -1;
    }
    __syncthreads();

    const float* w1e = w1 + (size_t)e * M_ * H_;
    u64 acc2[8][4];
#pragma unroll
    for (int i = 0; i < 8; i++)
#pragma unroll
        for (int j = 0; j < 4; j++) acc2[i][j] = 0ull;

    int tx = tid & 15;   // N quads
    int ty = tid >> 4;   // M quads

    for (int k0 = 0; k0 < M_; k0 += 16) {
#pragma unroll
        for (int i = 0; i < 2; i++) {
            int slot = tid + i * 256;          // 512 slots = 128 rows x 4
            int row = slot >> 2;
            int kk  = (slot & 3) * 4;
            float4 v = make_float4(0.f, 0.f, 0.f, 0.f);
            int t = tok[row];
            if (t >= 0) v = *(const float4*)(x + (size_t)t * M_ + k0 + kk);
            As[kk + 0][row] = v.x; As[kk + 1][row] = v.y;
            As[kk + 2][row] = v.z; As[kk + 3][row] = v.w;
        }
#pragma unroll
        for (int i = 0; i < 2; i++) {
            int slot = tid + i * 256;          // 512 slots = 16 k x 32
            int bk = slot >> 5;
            int bn = (slot & 31) * 4;
            *(float4*)&Bs[bk][bn] =
                *(const float4*)(w1e + (size_t)(k0 + bk) * H_ + n0 + bn);
        }
        __syncthreads();
        inner_tile(As, Bs, tx, ty, acc2);
        __syncthreads();
    }

    const float* b1e = b1 + e * H_;
#pragma unroll
    for (int i = 0; i < 8; i++) {
        int r = m0 + (i < 4 ? ty * 4 + i : 64 + ty * 4 + (i - 4));
        if (r < kept) {
            float* hrow = g_h + ((size_t)e * CAP + r) * H_;
#pragma unroll
            for (int j = 0; j < 4; j++) {
                int n = n0 + (j < 2 ? tx * 4 + j * 2 : 64 + tx * 4 + (j - 2) * 2);
                float p0 = __uint_as_float((uint32_t)acc2[i][j]);
                float p1 = __uint_as_float((uint32_t)(acc2[i][j] >> 32));
                float v0 = p0 + b1e[n];
                float v1 = p1 + b1e[n + 1];
                float u0 = 0.7978845608028654f * (v0 + 0.044715f * v0 * v0 * v0);
                float u1 = 0.7978845608028654f * (v1 + 0.044715f * v1 * v1 * v1);
                hrow[n]     = 0.5f * v0 * (1.0f + tanhf(u0));
                hrow[n + 1] = 0.5f * v1 * (1.0f + tanhf(u1));
            }
        }
    }
}

// ---------------- GEMM2: out[token] = (h @ w2[e] + b2[e]) * gate --------------------
__global__ __launch_bounds__(256) void gemm2_kernel(const float* __restrict__ w2,
                                                    const float* __restrict__ b2,
                                                    float* __restrict__ out,
                                                    int capacity) {
    const int e = blockIdx.z;
    const int kept = g_kept[e];
    const int m0 = blockIdx.y * 128;
    if (m0 >= kept) return;
    const int n0 = blockIdx.x * 128;

    __shared__ float As[16][SROW];
    __shared__ float Bs[16][SROW];

    int tid = threadIdx.x;
    const float* w2e  = w2 + (size_t)e * H_ * M_;
    const float* hblk = g_h + ((size_t)e * CAP + m0) * H_;

    u64 acc2[8][4];
#pragma unroll
    for (int i = 0; i < 8; i++)
#pragma unroll
        for (int j = 0; j < 4; j++) acc2[i][j] = 0ull;

    int tx = tid & 15;
    int ty = tid >> 4;

    for (int k0 = 0; k0 < H_; k0 += 16) {
#pragma unroll
        for (int i = 0; i < 2; i++) {
            int slot = tid + i * 256;
            int row = slot >> 2;
            int kk  = (slot & 3) * 4;
            // rows >= kept read stale scratch; results for them are never stored
            float4 v = *(const float4*)(hblk + (size_t)row * H_ + k0 + kk);
            As[kk + 0][row] = v.x; As[kk + 1][row] = v.y;
            As[kk + 2][row] = v.z; As[kk + 3][row] = v.w;
        }
#pragma unroll
        for (int i = 0; i < 2; i++) {
            int slot = tid + i * 256;
            int bk = slot >> 5;
            int bn = (slot & 31) * 4;
            *(float4*)&Bs[bk][bn] =
                *(const float4*)(w2e + (size_t)(k0 + bk) * M_ + n0 + bn);
        }
        __syncthreads();
        inner_tile(As, Bs, tx, ty, acc2);
        __syncthreads();
    }

    const float* b2e = b2 + e * M_;
#pragma unroll
    for (int i = 0; i < 8; i++) {
        int r = m0 + (i < 4 ? ty * 4 + i : 64 + ty * 4 + (i - 4));
        if (r < kept) {
            int t = g_slot_token[e * capacity + r];
            float gate = g_slot_gate[e * capacity + r];
            float* orow = out + (size_t)t * M_;
#pragma unroll
            for (int j = 0; j < 4; j++) {
                int n = n0 + (j < 2 ? tx * 4 + j * 2 : 64 + tx * 4 + (j - 2) * 2);
                float p0 = __uint_as_float((uint32_t)acc2[i][j]);
                float p1 = __uint_as_float((uint32_t)(acc2[i][j] >> 32));
                orow[n]     = (p0 + b2e[n])     * gate;
                orow[n + 1] = (p1 + b2e[n + 1]) * gate;
            }
        }
    }
}

// ---------------- launch -------------------------------------------------------
extern "C" void kernel_launch(void* const* d_in, const int* in_sizes, int n_in,
                              void* d_out, int out_size) {
    const float* x  = (const float*)d_in[0];
    const float* wg = (const float*)d_in[1];
    const float* w1 = (const float*)d_in[2];
    const float* b1 = (const float*)d_in[3];
    const float* w2 = (const float*)d_in[4];
    const float* b2 = (const float*)d_in[5];
    float* out = (float*)d_out;

    int s = in_sizes[0] / M_;
    int capacity = (s + E_ - 1) / E_;
    if (capacity < 4) capacity = 4;
    if (capacity > CAP) capacity = CAP;

    cudaMemsetAsync(d_out, 0, (size_t)out_size * sizeof(float), 0);

    init_kernel<<<1, 32>>>();
    gate_kernel<<<(s + 7) / 8, 256>>>(x, wg, s);
    scan_kernel<<<1, 256>>>(s, capacity, out, (long long)out_size);

    dim3 g1(H_ / 128, (capacity + 127) / 128, E_);
    gemm1_kernel<<<g1, 256>>>(x, w1, b1, capacity);

    dim3 g2(M_ / 128, (capacity + 127) / 128, E_);
    gemm2_kernel<<<g2, 256>>>(w2, b2, out, capacity);
}